// round 16
// baseline (speedup 1.0000x reference)
#include <cuda_runtime.h>
#include <cuda_fp16.h>
#include <cstdint>

#define NHEADS 8
#define NELEM 2097152   // 8*4096*64
// Q carries 0.125 * log2(e) so exp(S) == ex2(S').
#define QSCALE 0.18033688011112042f
__device__ unsigned long long g_keep_bits[NHEADS][64];
__device__ __align__(128) __half gQh[NELEM], gQl[NELEM];   // fp16 hi/lo of q*QSCALE
__device__ __align__(128) __half gKh[NELEM], gKl[NELEM];   // fp16 hi/lo of k
__device__ __align__(128) __half gVh[NELEM];               // fp16(v)

// ---------------- helpers ----------------
__device__ __forceinline__ uint32_t smem_u32(const void* p) {
    uint32_t a;
    asm("{ .reg .u64 t; cvta.to.shared.u64 t, %1; cvt.u32.u64 %0, t; }" : "=r"(a) : "l"(p));
    return a;
}
__device__ __forceinline__ float ex2f(float x) {
    float y;
    asm("ex2.approx.ftz.f32 %0, %1;" : "=f"(y) : "f"(x));
    return y;
}
__device__ __forceinline__ void ldm_x4(uint32_t* d, uint32_t addr) {
    asm volatile("ldmatrix.sync.aligned.m8n8.x4.shared.b16 {%0,%1,%2,%3}, [%4];"
                 : "=r"(d[0]), "=r"(d[1]), "=r"(d[2]), "=r"(d[3]) : "r"(addr));
}
__device__ __forceinline__ void ldm_x4_t(uint32_t* d, uint32_t addr) {
    asm volatile("ldmatrix.sync.aligned.m8n8.x4.trans.shared.b16 {%0,%1,%2,%3}, [%4];"
                 : "=r"(d[0]), "=r"(d[1]), "=r"(d[2]), "=r"(d[3]) : "r"(addr));
}
__device__ __forceinline__ void mma16816(float* c, const uint32_t* a, uint32_t b0, uint32_t b1) {
    asm volatile(
        "mma.sync.aligned.m16n8k16.row.col.f32.f16.f16.f32 "
        "{%0,%1,%2,%3}, {%4,%5,%6,%7}, {%8,%9}, {%0,%1,%2,%3};"
        : "+f"(c[0]), "+f"(c[1]), "+f"(c[2]), "+f"(c[3])
        : "r"(a[0]), "r"(a[1]), "r"(a[2]), "r"(a[3]), "r"(b0), "r"(b1));
}
__device__ __forceinline__ uint32_t pack2h(float a, float b) {
    __half2 hh = __floats2half2_rn(a, b);
    return *reinterpret_cast<uint32_t*>(&hh);
}
__device__ __forceinline__ void split2h(float a, float b, uint32_t& h, uint32_t& l) {
    __half ha = __float2half_rn(a), hb = __float2half_rn(b);
    __half la = __float2half_rn(a - __half2float(ha));
    __half lb = __float2half_rn(b - __half2float(hb));
    h = (uint32_t)__half_as_ushort(ha) | ((uint32_t)__half_as_ushort(hb) << 16);
    l = (uint32_t)__half_as_ushort(la) | ((uint32_t)__half_as_ushort(lb) << 16);
}
__device__ __forceinline__ void cp16(uint32_t dst, const void* src) {
    asm volatile("cp.async.cg.shared.global [%0], [%1], 16;" :: "r"(dst), "l"(src));
}
#define CP_COMMIT() asm volatile("cp.async.commit_group;" ::: "memory")

// ---------------------------------------------------------------------------
// Kernel 0: convert Q (xQSCALE, hi/lo), K (hi/lo), V (fp16) global arrays.
// ---------------------------------------------------------------------------
__global__ __launch_bounds__(256) void split_prepass(
    const float* __restrict__ q, const float* __restrict__ k, const float* __restrict__ v)
{
    const int idx = (blockIdx.x * 256 + threadIdx.x) * 8;
    float4 a, b; uint32_t hw[4], lw[4];

    a = *(const float4*)(q + idx); b = *(const float4*)(q + idx + 4);
    split2h(a.x * QSCALE, a.y * QSCALE, hw[0], lw[0]);
    split2h(a.z * QSCALE, a.w * QSCALE, hw[1], lw[1]);
    split2h(b.x * QSCALE, b.y * QSCALE, hw[2], lw[2]);
    split2h(b.z * QSCALE, b.w * QSCALE, hw[3], lw[3]);
    *(uint4*)(gQh + idx) = make_uint4(hw[0], hw[1], hw[2], hw[3]);
    *(uint4*)(gQl + idx) = make_uint4(lw[0], lw[1], lw[2], lw[3]);

    a = *(const float4*)(k + idx); b = *(const float4*)(k + idx + 4);
    split2h(a.x, a.y, hw[0], lw[0]); split2h(a.z, a.w, hw[1], lw[1]);
    split2h(b.x, b.y, hw[2], lw[2]); split2h(b.z, b.w, hw[3], lw[3]);
    *(uint4*)(gKh + idx) = make_uint4(hw[0], hw[1], hw[2], hw[3]);
    *(uint4*)(gKl + idx) = make_uint4(lw[0], lw[1], lw[2], lw[3]);

    a = *(const float4*)(v + idx); b = *(const float4*)(v + idx + 4);
    *(uint4*)(gVh + idx) = make_uint4(
        pack2h(a.x, a.y), pack2h(a.z, a.w), pack2h(b.x, b.y), pack2h(b.z, b.w));
}

// ---------------------------------------------------------------------------
// Kernel 1: pooled sampled attention, split-K across two warp-groups.
// (Unchanged R14: 256 thr, wg0 k-tiles 0-7, wg1 8-15, fused rank tail.)
// Smem: SQh 0, SQl 9216; per-wg K: base 18432 + wg*36864. Total 92160 B.
// ---------------------------------------------------------------------------
#define TS 72

__global__ __launch_bounds__(256) void pool_gemm_kernel(
    const int* __restrict__ sidq, const int* __restrict__ sidk)
{
    const int qt = blockIdx.x, h = blockIdx.y;
    const int t = threadIdx.x, w = t >> 5, lane = t & 31;
    const int wg = t >> 7, wi = w & 3, wgt = t & 127;

    extern __shared__ __half sm[];
    __shared__ int sqi[16], ski16[16];
    __shared__ float pv[4][64];
    __shared__ float lbuf[8][8][2];

    const uint32_t b0 = smem_u32(sm);
    const uint32_t SQh = b0, SQl = b0 + 9216u;
    const uint32_t kbase = b0 + 18432u + (uint32_t)wg * 36864u;
    const uint32_t skh[2] = { kbase, kbase + 18432u };
    const uint32_t skl[2] = { kbase + 9216u, kbase + 27648u };

    if (t < 16) { sqi[t] = sidq[h * 16 + t]; ski16[t] = sidk[h * 16 + t]; }
    __syncthreads();

    const int r2 = wgt >> 1, half = wgt & 1;
    const uint32_t rowoff = (uint32_t)(r2 * 144 + half * 64);

    {
        const int grow = ((qt << 2) + (r2 >> 4)) * 64 + sqi[r2 & 15];
        const int g = (((h << 12) + grow) << 6) + half * 32;
        const uint32_t dstQ = wg ? SQl : SQh;
        const __half* srcQ = wg ? gQl : gQh;
        #pragma unroll
        for (int c = 0; c < 4; c++)
            cp16(dstQ + rowoff + c * 16, srcQ + g + c * 8);
    }
    CP_COMMIT();
    {
        const int kt = wg * 8;
        const int grow = ((kt << 2) + (r2 >> 4)) * 64 + ski16[r2 & 15];
        const int g = (((h << 12) + grow) << 6) + half * 32;
        #pragma unroll
        for (int c = 0; c < 4; c++) {
            cp16(skh[0] + rowoff + c * 16, gKh + g + c * 8);
            cp16(skl[0] + rowoff + c * 16, gKl + g + c * 8);
        }
    }
    CP_COMMIT();
    asm volatile("cp.async.wait_group 1;" ::: "memory");
    __syncthreads();

    const int m0 = wi * 16;
    uint32_t qfh[4][4], qfl[4][4];
    {
        const int mat = lane >> 3, mr = lane & 7;
        const int arow = m0 + ((mat & 1) << 3) + mr;
        const int acol0 = (mat >> 1) << 3;
        #pragma unroll
        for (int ks = 0; ks < 4; ks++) {
            ldm_x4(qfh[ks], SQh + (uint32_t)(arow * TS + 16 * ks + acol0) * 2);
            ldm_x4(qfl[ks], SQl + (uint32_t)(arow * TS + 16 * ks + acol0) * 2);
        }
    }

    float Ef[4][4] = {};
    float lsum0 = 0.f, lsum1 = 0.f;
    const int g8 = (lane >> 3) << 3;
    const int lr = lane & 7;
    const int myn = lane >> 2;

    for (int it = 0; it < 8; it++) {
        const int cur = it & 1;
        if (it + 1 < 8) {
            const int kt = wg * 8 + it + 1;
            const int grow = ((kt << 2) + (r2 >> 4)) * 64 + ski16[r2 & 15];
            const int g = (((h << 12) + grow) << 6) + half * 32;
            #pragma unroll
            for (int c = 0; c < 4; c++) {
                cp16(skh[cur ^ 1] + rowoff + c * 16, gKh + g + c * 8);
                cp16(skl[cur ^ 1] + rowoff + c * 16, gKl + g + c * 8);
            }
        }
        CP_COMMIT();
        asm volatile("cp.async.wait_group 1;" ::: "memory");
        __syncthreads();

        const uint32_t kh = skh[cur], kl = skl[cur];

        float sC[8][4] = {};
        #pragma unroll
        for (int kk = 0; kk < 2; kk++) {
            #pragma unroll
            for (int nt = 0; nt < 8; nt++) {
                uint32_t baddr = (uint32_t)((8 * nt + lr) * TS + 32 * kk + g8) * 2;
                uint32_t bh[4], bl[4];
                ldm_x4(bh, kh + baddr);
                ldm_x4(bl, kl + baddr);
                mma16816(sC[nt], qfh[2 * kk],     bh[0], bh[1]);
                mma16816(sC[nt], qfh[2 * kk + 1], bh[2], bh[3]);
                mma16816(sC[nt], qfh[2 * kk],     bl[0], bl[1]);
                mma16816(sC[nt], qfh[2 * kk + 1], bl[2], bl[3]);
                mma16816(sC[nt], qfl[2 * kk],     bh[0], bh[1]);
                mma16816(sC[nt], qfl[2 * kk + 1], bh[2], bh[3]);
            }
        }

        uint32_t ph[8][2], pl[8][2];
        #pragma unroll
        for (int nt = 0; nt < 8; nt++) {
            float p0 = ex2f(sC[nt][0]), p1 = ex2f(sC[nt][1]);
            float p2 = ex2f(sC[nt][2]), p3 = ex2f(sC[nt][3]);
            lsum0 += p0 + p1; lsum1 += p2 + p3;
            split2h(p0, p1, ph[nt][0], pl[nt][0]);
            split2h(p2, p3, ph[nt][1], pl[nt][1]);
        }

        const int tgt_base = (it & 1) << 2;
        float* Edst = Ef[it >> 1];
        #pragma unroll
        for (int kk16 = 0; kk16 < 4; kk16++) {
            uint32_t sel = (myn == tgt_base + kk16) ? 0x3C003C00u : 0u;
            uint32_t pA[4] = { ph[2*kk16][0], ph[2*kk16][1], ph[2*kk16+1][0], ph[2*kk16+1][1] };
            uint32_t lA[4] = { pl[2*kk16][0], pl[2*kk16][1], pl[2*kk16+1][0], pl[2*kk16+1][1] };
            mma16816(Edst, pA, sel, sel);
            mma16816(Edst, lA, sel, sel);
        }
        __syncthreads();
    }

    #pragma unroll
    for (int off = 1; off < 4; off <<= 1) {
        lsum0 += __shfl_xor_sync(0xffffffffu, lsum0, off, 4);
        lsum1 += __shfl_xor_sync(0xffffffffu, lsum1, off, 4);
    }
    if ((lane & 3) == 0) {
        lbuf[w][lane >> 2][0] = lsum0;
        lbuf[w][lane >> 2][1] = lsum1;
    }
    __syncthreads();
    const float inv0 = 1.f / (lsum0 + lbuf[w ^ 4][lane >> 2][0]);
    const float inv1 = 1.f / (lsum1 + lbuf[w ^ 4][lane >> 2][1]);

    #pragma unroll
    for (int t4 = 0; t4 < 4; t4++) {
        float v0 = Ef[t4][0] * inv0 + Ef[t4][2] * inv1;
        float v1 = Ef[t4][1] * inv0 + Ef[t4][3] * inv1;
        #pragma unroll
        for (int off = 4; off < 32; off <<= 1) {
            v0 += __shfl_xor_sync(0xffffffffu, v0, off);
            v1 += __shfl_xor_sync(0xffffffffu, v1, off);
        }
        if (lane < 4) {
            const int kb = wg * 32 + 8 * t4 + 2 * lane;
            pv[wi][kb]     = v0;
            pv[wi][kb + 1] = v1;
        }
    }
    __syncthreads();

    if (w < 4) {
        const float* p = pv[w];
        float tot = 0.f;
        for (int j = 0; j < 64; j++) tot += p[j];
        const float m1 = p[lane], m2 = p[lane + 32];
        float b1 = 0.f, b2 = 0.f;
        for (int j = 0; j < 64; j++) {
            float pj = p[j];
            if (pj > m1 || (pj == m1 && j < lane))      b1 += pj;
            if (pj > m2 || (pj == m2 && j < lane + 32)) b2 += pj;
        }
        const float thr = 0.5f * tot;
        uint32_t lo = __ballot_sync(0xffffffffu, b1 < thr);
        uint32_t hi = __ballot_sync(0xffffffffu, b2 < thr);
        if (lane == 0)
            g_keep_bits[h][(qt << 2) + w] =
                (unsigned long long)lo | ((unsigned long long)hi << 32);
    }
}

// ---------------------------------------------------------------------------
// Kernel 2: block-sparse attention, single-term fp16 mma.sync.
// R14 K schedule (double-buffered, slack 1, wait after commit); V TRIPLE-
// buffered with V(it+1) committed at the TOP of iter it (slack ~1.5 iters)
// while the V-wait stays AFTER the exp phase. Race-free without a tail sync:
// the V commit at top of it+1 targets vhB[(it+2)%3]=vhB[(it-1)%3], whose
// readers (PV(it-1)) are separated from the writer by two barriers.
// Groups/iter: [K(it+1)], [V(it+1)] -> top wait_group 3 (K(it)), mid
// wait_group 2 (V(it)); tail indices clamped so counts stay uniform.
// Smem (bytes, tile=9216): Qh/kh1=0 kh0=9216 vh0=18432 vh1=27648 vh2=36864.
// Total 46080 B -> 4 CTAs/SM.
// ---------------------------------------------------------------------------
__global__ __launch_bounds__(128, 4) void attn_hmma_kernel(float* __restrict__ out)
{
    const int qb = blockIdx.x, h = blockIdx.y;
    const int t = threadIdx.x, w = t >> 5, lane = t & 31;

    extern __shared__ __half sm[];
    __shared__ int ulist[64];
    __shared__ int ucnt_s;

    const uint32_t b0 = smem_u32(sm);
    const uint32_t qhB = b0;
    const uint32_t khB[2] = { b0 + 9216u, b0 };
    const uint32_t vhB[3] = { b0 + 18432u, b0 + 27648u, b0 + 36864u };

    if (t == 0) {
        unsigned long long u = g_keep_bits[h][qb];
        int c = 0;
        for (int b = 0; b < 64; b++) if ((u >> b) & 1ull) ulist[c++] = b;
        ucnt_s = c;
    }

    const int r2 = t >> 1, half = t & 1;
    const uint32_t rowoff = (uint32_t)(r2 * 144 + half * 64);
    {
        const int gq = ((((h << 12) + (qb << 6) + r2) << 6) + half * 32);
        #pragma unroll
        for (int c = 0; c < 4; c++) cp16(qhB + rowoff + c * 16, gQh + gq + c * 8);
    }
    CP_COMMIT();
    asm volatile("cp.async.wait_group 0;" ::: "memory");
    __syncthreads();
    const int ucnt = ucnt_s;

    // Prologue groups: K(0) into khB[0], V(0) into vhB[0]. Neither touches Q.
    {
        const int kb = ulist[0];
        const int g = ((((h << 12) + (kb << 6) + r2) << 6) + half * 32);
        #pragma unroll
        for (int c = 0; c < 4; c++)
            cp16(khB[0] + rowoff + c * 16, gKh + g + c * 8);
    }
    CP_COMMIT();
    {
        const int kb = ulist[0];
        const int g = ((((h << 12) + (kb << 6) + r2) << 6) + half * 32);
        #pragma unroll
        for (int c = 0; c < 4; c++)
            cp16(vhB[0] + rowoff + c * 16, gVh + g + c * 8);
    }
    CP_COMMIT();

    // Q fragments (persistent).
    const int m0 = w * 16;
    uint32_t qf[4][4];
    {
        const int mat = lane >> 3, mr = lane & 7;
        const int arow = m0 + ((mat & 1) << 3) + mr;
        const int acol0 = (mat >> 1) << 3;
        #pragma unroll
        for (int ks = 0; ks < 4; ks++)
            ldm_x4(qf[ks], qhB + (uint32_t)(arow * TS + 16 * ks + acol0) * 2);
    }
    __syncthreads();   // Q fragments extracted before K(1) prefetch overwrites Q region

    float oAcc[8][4] = {};
    float lsum0 = 0.f, lsum1 = 0.f;
    const int g8 = (lane >> 3) << 3;
    const int lr = lane & 7;

    int vslot = 0;       // it % 3
    int vslot1 = 1;      // (it+1) % 3
    for (int it = 0; it < ucnt; it++) {
        const int cur = it & 1;
        const int nidx = (it + 1 < ucnt) ? it + 1 : ucnt - 1;  // clamped
        // Top: commit K(it+1) then V(it+1), each its own group.
        {
            const int kb = ulist[nidx];
            const int g = ((((h << 12) + (kb << 6) + r2) << 6) + half * 32);
            #pragma unroll
            for (int c = 0; c < 4; c++)
                cp16(khB[cur ^ 1] + rowoff + c * 16, gKh + g + c * 8);
        }
        CP_COMMIT();
        {
            const int kb = ulist[nidx];
            const int g = ((((h << 12) + (kb << 6) + r2) << 6) + half * 32);
            #pragma unroll
            for (int c = 0; c < 4; c++)
                cp16(vhB[vslot1] + rowoff + c * 16, gVh + g + c * 8);
        }
        CP_COMMIT();
        asm volatile("cp.async.wait_group 3;" ::: "memory");  // K(it) landed
        __syncthreads();

        const uint32_t kh = khB[cur];

        // ---- S = Qh Kh^T.
        float sC[8][4] = {};
        #pragma unroll
        for (int kk = 0; kk < 2; kk++) {
            #pragma unroll
            for (int nt = 0; nt < 8; nt++) {
                uint32_t baddr = (uint32_t)((8 * nt + lr) * TS + 32 * kk + g8) * 2;
                uint32_t bh[4];
                ldm_x4(bh, kh + baddr);
                mma16816(sC[nt], qf[2 * kk],     bh[0], bh[1]);
                mma16816(sC[nt], qf[2 * kk + 1], bh[2], bh[3]);
            }
        }

        // ---- ex2, l accumulate, pack P (single fp16).
        uint32_t ph[8][2];
        #pragma unroll
        for (int nt = 0; nt < 8; nt++) {
            float p0 = ex2f(sC[nt][0]), p1 = ex2f(sC[nt][1]);
            float p2 = ex2f(sC[nt][2]), p3 = ex2f(sC[nt][3]);
            lsum0 += p0 + p1; lsum1 += p2 + p3;
            ph[nt][0] = pack2h(p0, p1);
            ph[nt][1] = pack2h(p2, p3);
        }

        asm volatile("cp.async.wait_group 2;" ::: "memory");  // V(it) landed
        __syncthreads();

        // ---- O += Ph Vh.
        #pragma unroll
        for (int kk = 0; kk < 2; kk++) {
            uint32_t pa0[4] = { ph[4*kk][0], ph[4*kk][1], ph[4*kk+1][0], ph[4*kk+1][1] };
            uint32_t pa1[4] = { ph[4*kk+2][0], ph[4*kk+2][1], ph[4*kk+3][0], ph[4*kk+3][1] };
            #pragma unroll
            for (int nt = 0; nt < 8; nt++) {
                uint32_t baddr = (uint32_t)((32 * kk + g8 + lr) * TS + 8 * nt) * 2;
                uint32_t bh[4];
                ldm_x4_t(bh, vhB[vslot] + baddr);
                mma16816(oAcc[nt], pa0, bh[0], bh[1]);
                mma16816(oAcc[nt], pa1, bh[2], bh[3]);
            }
        }
        // no tail sync: next iter's K commit targets khB[cur] (S readers all
        // passed this iter's mid-sync) and its V commit targets
        // vhB[(it+2)%3]=vhB[(it-1)%3] (PV(it-1) readers are 2 barriers back).
        vslot  = (vslot  == 2) ? 0 : vslot + 1;
        vslot1 = (vslot1 == 2) ? 0 : vslot1 + 1;
    }

    #pragma unroll
    for (int off = 1; off < 4; off <<= 1) {
        lsum0 += __shfl_xor_sync(0xffffffffu, lsum0, off, 4);
        lsum1 += __shfl_xor_sync(0xffffffffu, lsum1, off, 4);
    }
    const float inv0 = 1.f / lsum0, inv1 = 1.f / lsum1;

    {
        const int r0 = (qb << 6) + m0 + (lane >> 2);
        const int cc = (lane & 3) << 1;
        float* o0 = out + (((h << 12) + r0) << 6) + cc;
        float* o1 = o0 + (8 << 6);
        #pragma unroll
        for (int nt = 0; nt < 8; nt++) {
            *(float2*)(o0 + 8 * nt) = make_float2(oAcc[nt][0] * inv0, oAcc[nt][1] * inv0);
            *(float2*)(o1 + 8 * nt) = make_float2(oAcc[nt][2] * inv1, oAcc[nt][3] * inv1);
        }
    }
}

extern "C" void kernel_launch(void* const* d_in, const int* in_sizes, int n_in,
                              void* d_out, int out_size) {
    const float* q  = (const float*)d_in[0];
    const float* k  = (const float*)d_in[1];
    const float* v  = (const float*)d_in[2];
    const int* siq  = (const int*)d_in[3];
    const int* sik  = (const int*)d_in[4];
    float* out = (float*)d_out;

    const int pool_smem = 92160;
    const int attn_smem = 46080;
    cudaFuncSetAttribute(pool_gemm_kernel, cudaFuncAttributeMaxDynamicSharedMemorySize, pool_smem);
    cudaFuncSetAttribute(attn_hmma_kernel, cudaFuncAttributeMaxDynamicSharedMemorySize, attn_smem);

    split_prepass<<<1024, 256>>>(q, k, v);
    pool_gemm_kernel<<<dim3(16, 8), 256, pool_smem>>>(siq, sik);
    attn_hmma_kernel<<<dim3(64, 8), 128, attn_smem>>>(out);
}

// round 17
// speedup vs baseline: 1.0355x; 1.0355x over previous
#include <cuda_runtime.h>
#include <cuda_fp16.h>
#include <cstdint>

#define NHEADS 8
#define NELEM 2097152   // 8*4096*64
// Q carries 0.125 * log2(e) so exp(S) == ex2(S').
#define QSCALE 0.18033688011112042f
__device__ unsigned long long g_keep_bits[NHEADS][64];
__device__ __align__(128) __half gQh[NELEM], gQl[NELEM];   // fp16 hi/lo of q*QSCALE
__device__ __align__(128) __half gKh[NELEM], gKl[NELEM];   // fp16 hi/lo of k
__device__ __align__(128) __half gVh[NELEM];               // fp16(v)

// ---------------- helpers ----------------
__device__ __forceinline__ uint32_t smem_u32(const void* p) {
    uint32_t a;
    asm("{ .reg .u64 t; cvta.to.shared.u64 t, %1; cvt.u32.u64 %0, t; }" : "=r"(a) : "l"(p));
    return a;
}
__device__ __forceinline__ float ex2f(float x) {
    float y;
    asm("ex2.approx.ftz.f32 %0, %1;" : "=f"(y) : "f"(x));
    return y;
}
__device__ __forceinline__ void ldm_x4(uint32_t* d, uint32_t addr) {
    asm volatile("ldmatrix.sync.aligned.m8n8.x4.shared.b16 {%0,%1,%2,%3}, [%4];"
                 : "=r"(d[0]), "=r"(d[1]), "=r"(d[2]), "=r"(d[3]) : "r"(addr));
}
__device__ __forceinline__ void ldm_x4_t(uint32_t* d, uint32_t addr) {
    asm volatile("ldmatrix.sync.aligned.m8n8.x4.trans.shared.b16 {%0,%1,%2,%3}, [%4];"
                 : "=r"(d[0]), "=r"(d[1]), "=r"(d[2]), "=r"(d[3]) : "r"(addr));
}
__device__ __forceinline__ void mma16816(float* c, const uint32_t* a, uint32_t b0, uint32_t b1) {
    asm volatile(
        "mma.sync.aligned.m16n8k16.row.col.f32.f16.f16.f32 "
        "{%0,%1,%2,%3}, {%4,%5,%6,%7}, {%8,%9}, {%0,%1,%2,%3};"
        : "+f"(c[0]), "+f"(c[1]), "+f"(c[2]), "+f"(c[3])
        : "r"(a[0]), "r"(a[1]), "r"(a[2]), "r"(a[3]), "r"(b0), "r"(b1));
}
__device__ __forceinline__ uint32_t pack2h(float a, float b) {
    __half2 hh = __floats2half2_rn(a, b);
    return *reinterpret_cast<uint32_t*>(&hh);
}
__device__ __forceinline__ void split2h(float a, float b, uint32_t& h, uint32_t& l) {
    __half ha = __float2half_rn(a), hb = __float2half_rn(b);
    __half la = __float2half_rn(a - __half2float(ha));
    __half lb = __float2half_rn(b - __half2float(hb));
    h = (uint32_t)__half_as_ushort(ha) | ((uint32_t)__half_as_ushort(hb) << 16);
    l = (uint32_t)__half_as_ushort(la) | ((uint32_t)__half_as_ushort(lb) << 16);
}
__device__ __forceinline__ void cp16(uint32_t dst, const void* src) {
    asm volatile("cp.async.cg.shared.global [%0], [%1], 16;" :: "r"(dst), "l"(src));
}
#define CP_COMMIT() asm volatile("cp.async.commit_group;" ::: "memory")

// ---------------------------------------------------------------------------
// Kernel 0: convert Q (xQSCALE, hi/lo), K (hi/lo), V (fp16) global arrays.
// ---------------------------------------------------------------------------
__global__ __launch_bounds__(256) void split_prepass(
    const float* __restrict__ q, const float* __restrict__ k, const float* __restrict__ v)
{
    const int idx = (blockIdx.x * 256 + threadIdx.x) * 8;
    float4 a, b; uint32_t hw[4], lw[4];

    a = *(const float4*)(q + idx); b = *(const float4*)(q + idx + 4);
    split2h(a.x * QSCALE, a.y * QSCALE, hw[0], lw[0]);
    split2h(a.z * QSCALE, a.w * QSCALE, hw[1], lw[1]);
    split2h(b.x * QSCALE, b.y * QSCALE, hw[2], lw[2]);
    split2h(b.z * QSCALE, b.w * QSCALE, hw[3], lw[3]);
    *(uint4*)(gQh + idx) = make_uint4(hw[0], hw[1], hw[2], hw[3]);
    *(uint4*)(gQl + idx) = make_uint4(lw[0], lw[1], lw[2], lw[3]);

    a = *(const float4*)(k + idx); b = *(const float4*)(k + idx + 4);
    split2h(a.x, a.y, hw[0], lw[0]); split2h(a.z, a.w, hw[1], lw[1]);
    split2h(b.x, b.y, hw[2], lw[2]); split2h(b.z, b.w, hw[3], lw[3]);
    *(uint4*)(gKh + idx) = make_uint4(hw[0], hw[1], hw[2], hw[3]);
    *(uint4*)(gKl + idx) = make_uint4(lw[0], lw[1], lw[2], lw[3]);

    a = *(const float4*)(v + idx); b = *(const float4*)(v + idx + 4);
    *(uint4*)(gVh + idx) = make_uint4(
        pack2h(a.x, a.y), pack2h(a.z, a.w), pack2h(b.x, b.y), pack2h(b.z, b.w));
}

// ---------------------------------------------------------------------------
// Kernel 1: pooled sampled attention, split-K across two warp-groups.
// (Unchanged R14: 256 thr, wg0 k-tiles 0-7, wg1 8-15, fused rank tail.)
// Smem: SQh 0, SQl 9216; per-wg K: base 18432 + wg*36864. Total 92160 B.
// ---------------------------------------------------------------------------
#define TS 72

__global__ __launch_bounds__(256) void pool_gemm_kernel(
    const int* __restrict__ sidq, const int* __restrict__ sidk)
{
    const int qt = blockIdx.x, h = blockIdx.y;
    const int t = threadIdx.x, w = t >> 5, lane = t & 31;
    const int wg = t >> 7, wi = w & 3, wgt = t & 127;

    extern __shared__ __half sm[];
    __shared__ int sqi[16], ski16[16];
    __shared__ float pv[4][64];
    __shared__ float lbuf[8][8][2];

    const uint32_t b0 = smem_u32(sm);
    const uint32_t SQh = b0, SQl = b0 + 9216u;
    const uint32_t kbase = b0 + 18432u + (uint32_t)wg * 36864u;
    const uint32_t skh[2] = { kbase, kbase + 18432u };
    const uint32_t skl[2] = { kbase + 9216u, kbase + 27648u };

    if (t < 16) { sqi[t] = sidq[h * 16 + t]; ski16[t] = sidk[h * 16 + t]; }
    __syncthreads();

    const int r2 = wgt >> 1, half = wgt & 1;
    const uint32_t rowoff = (uint32_t)(r2 * 144 + half * 64);

    {
        const int grow = ((qt << 2) + (r2 >> 4)) * 64 + sqi[r2 & 15];
        const int g = (((h << 12) + grow) << 6) + half * 32;
        const uint32_t dstQ = wg ? SQl : SQh;
        const __half* srcQ = wg ? gQl : gQh;
        #pragma unroll
        for (int c = 0; c < 4; c++)
            cp16(dstQ + rowoff + c * 16, srcQ + g + c * 8);
    }
    CP_COMMIT();
    {
        const int kt = wg * 8;
        const int grow = ((kt << 2) + (r2 >> 4)) * 64 + ski16[r2 & 15];
        const int g = (((h << 12) + grow) << 6) + half * 32;
        #pragma unroll
        for (int c = 0; c < 4; c++) {
            cp16(skh[0] + rowoff + c * 16, gKh + g + c * 8);
            cp16(skl[0] + rowoff + c * 16, gKl + g + c * 8);
        }
    }
    CP_COMMIT();
    asm volatile("cp.async.wait_group 1;" ::: "memory");
    __syncthreads();

    const int m0 = wi * 16;
    uint32_t qfh[4][4], qfl[4][4];
    {
        const int mat = lane >> 3, mr = lane & 7;
        const int arow = m0 + ((mat & 1) << 3) + mr;
        const int acol0 = (mat >> 1) << 3;
        #pragma unroll
        for (int ks = 0; ks < 4; ks++) {
            ldm_x4(qfh[ks], SQh + (uint32_t)(arow * TS + 16 * ks + acol0) * 2);
            ldm_x4(qfl[ks], SQl + (uint32_t)(arow * TS + 16 * ks + acol0) * 2);
        }
    }

    float Ef[4][4] = {};
    float lsum0 = 0.f, lsum1 = 0.f;
    const int g8 = (lane >> 3) << 3;
    const int lr = lane & 7;
    const int myn = lane >> 2;

    for (int it = 0; it < 8; it++) {
        const int cur = it & 1;
        if (it + 1 < 8) {
            const int kt = wg * 8 + it + 1;
            const int grow = ((kt << 2) + (r2 >> 4)) * 64 + ski16[r2 & 15];
            const int g = (((h << 12) + grow) << 6) + half * 32;
            #pragma unroll
            for (int c = 0; c < 4; c++) {
                cp16(skh[cur ^ 1] + rowoff + c * 16, gKh + g + c * 8);
                cp16(skl[cur ^ 1] + rowoff + c * 16, gKl + g + c * 8);
            }
        }
        CP_COMMIT();
        asm volatile("cp.async.wait_group 1;" ::: "memory");
        __syncthreads();

        const uint32_t kh = skh[cur], kl = skl[cur];

        float sC[8][4] = {};
        #pragma unroll
        for (int kk = 0; kk < 2; kk++) {
            #pragma unroll
            for (int nt = 0; nt < 8; nt++) {
                uint32_t baddr = (uint32_t)((8 * nt + lr) * TS + 32 * kk + g8) * 2;
                uint32_t bh[4], bl[4];
                ldm_x4(bh, kh + baddr);
                ldm_x4(bl, kl + baddr);
                mma16816(sC[nt], qfh[2 * kk],     bh[0], bh[1]);
                mma16816(sC[nt], qfh[2 * kk + 1], bh[2], bh[3]);
                mma16816(sC[nt], qfh[2 * kk],     bl[0], bl[1]);
                mma16816(sC[nt], qfh[2 * kk + 1], bl[2], bl[3]);
                mma16816(sC[nt], qfl[2 * kk],     bh[0], bh[1]);
                mma16816(sC[nt], qfl[2 * kk + 1], bh[2], bh[3]);
            }
        }

        uint32_t ph[8][2], pl[8][2];
        #pragma unroll
        for (int nt = 0; nt < 8; nt++) {
            float p0 = ex2f(sC[nt][0]), p1 = ex2f(sC[nt][1]);
            float p2 = ex2f(sC[nt][2]), p3 = ex2f(sC[nt][3]);
            lsum0 += p0 + p1; lsum1 += p2 + p3;
            split2h(p0, p1, ph[nt][0], pl[nt][0]);
            split2h(p2, p3, ph[nt][1], pl[nt][1]);
        }

        const int tgt_base = (it & 1) << 2;
        float* Edst = Ef[it >> 1];
        #pragma unroll
        for (int kk16 = 0; kk16 < 4; kk16++) {
            uint32_t sel = (myn == tgt_base + kk16) ? 0x3C003C00u : 0u;
            uint32_t pA[4] = { ph[2*kk16][0], ph[2*kk16][1], ph[2*kk16+1][0], ph[2*kk16+1][1] };
            uint32_t lA[4] = { pl[2*kk16][0], pl[2*kk16][1], pl[2*kk16+1][0], pl[2*kk16+1][1] };
            mma16816(Edst, pA, sel, sel);
            mma16816(Edst, lA, sel, sel);
        }
        __syncthreads();
    }

    #pragma unroll
    for (int off = 1; off < 4; off <<= 1) {
        lsum0 += __shfl_xor_sync(0xffffffffu, lsum0, off, 4);
        lsum1 += __shfl_xor_sync(0xffffffffu, lsum1, off, 4);
    }
    if ((lane & 3) == 0) {
        lbuf[w][lane >> 2][0] = lsum0;
        lbuf[w][lane >> 2][1] = lsum1;
    }
    __syncthreads();
    const float inv0 = 1.f / (lsum0 + lbuf[w ^ 4][lane >> 2][0]);
    const float inv1 = 1.f / (lsum1 + lbuf[w ^ 4][lane >> 2][1]);

    #pragma unroll
    for (int t4 = 0; t4 < 4; t4++) {
        float v0 = Ef[t4][0] * inv0 + Ef[t4][2] * inv1;
        float v1 = Ef[t4][1] * inv0 + Ef[t4][3] * inv1;
        #pragma unroll
        for (int off = 4; off < 32; off <<= 1) {
            v0 += __shfl_xor_sync(0xffffffffu, v0, off);
            v1 += __shfl_xor_sync(0xffffffffu, v1, off);
        }
        if (lane < 4) {
            const int kb = wg * 32 + 8 * t4 + 2 * lane;
            pv[wi][kb]     = v0;
            pv[wi][kb + 1] = v1;
        }
    }
    __syncthreads();

    if (w < 4) {
        const float* p = pv[w];
        float tot = 0.f;
        for (int j = 0; j < 64; j++) tot += p[j];
        const float m1 = p[lane], m2 = p[lane + 32];
        float b1 = 0.f, b2 = 0.f;
        for (int j = 0; j < 64; j++) {
            float pj = p[j];
            if (pj > m1 || (pj == m1 && j < lane))      b1 += pj;
            if (pj > m2 || (pj == m2 && j < lane + 32)) b2 += pj;
        }
        const float thr = 0.5f * tot;
        uint32_t lo = __ballot_sync(0xffffffffu, b1 < thr);
        uint32_t hi = __ballot_sync(0xffffffffu, b2 < thr);
        if (lane == 0)
            g_keep_bits[h][(qt << 2) + w] =
                (unsigned long long)lo | ((unsigned long long)hi << 32);
    }
}

// ---------------------------------------------------------------------------
// Kernel 2: block-sparse attention, single-term fp16 mma.sync.
// EXACT R14 loop schedule (measured 108.0 total): K double-buffered (stage1
// reuses Q region), V double-buffered, V(it) committed in-iteration into
// vhB[cur] and waited after the exp phase; 2 syncthreads/iter, no tail sync.
// PDL: Q load + fragment extraction run BEFORE cudaGridDependencySynchronize
// (they read only prepass output, which is complete by transitivity of the
// normal prepass->pool edge); keep_bits is read only after the grid sync.
// Smem (bytes, tile=9216): Qh/kh1=0 kh0=9216 vh0=18432 vh1=27648. 36864 B.
// ---------------------------------------------------------------------------
__global__ __launch_bounds__(128, 4) void attn_hmma_kernel(float* __restrict__ out)
{
    const int qb = blockIdx.x, h = blockIdx.y;
    const int t = threadIdx.x, w = t >> 5, lane = t & 31;

    extern __shared__ __half sm[];
    __shared__ int ulist[64];
    __shared__ int ucnt_s;

    const uint32_t b0 = smem_u32(sm);
    const uint32_t qhB = b0;
    const uint32_t khB[2] = { b0 + 9216u, b0 };
    const uint32_t vhB[2] = { b0 + 18432u, b0 + 27648u };

    // ---- Pre-sync phase: depends only on prepass output (gQh). ----
    const int r2 = t >> 1, half = t & 1;
    const uint32_t rowoff = (uint32_t)(r2 * 144 + half * 64);
    {
        const int gq = ((((h << 12) + (qb << 6) + r2) << 6) + half * 32);
        #pragma unroll
        for (int c = 0; c < 4; c++) cp16(qhB + rowoff + c * 16, gQh + gq + c * 8);
    }
    CP_COMMIT();
    asm volatile("cp.async.wait_group 0;" ::: "memory");
    __syncthreads();

    // Q fragments (persistent).
    const int m0 = w * 16;
    uint32_t qf[4][4];
    {
        const int mat = lane >> 3, mr = lane & 7;
        const int arow = m0 + ((mat & 1) << 3) + mr;
        const int acol0 = (mat >> 1) << 3;
        #pragma unroll
        for (int ks = 0; ks < 4; ks++)
            ldm_x4(qf[ks], qhB + (uint32_t)(arow * TS + 16 * ks + acol0) * 2);
    }

    // ---- Grid sync: pool_gemm (keep_bits) must be complete past here. ----
    cudaGridDependencySynchronize();

    if (t == 0) {
        unsigned long long u = g_keep_bits[h][qb];
        int c = 0;
        for (int b = 0; b < 64; b++) if ((u >> b) & 1ull) ulist[c++] = b;
        ucnt_s = c;
    }
    __syncthreads();   // ulist visible + all Q fragments extracted before K(1)
                       // may overwrite the Q smem region (khB[1] == qhB).
    const int ucnt = ucnt_s;

    // Prefetch K(0) into stage-0 buffer (not the Q region).
    {
        const int kb = ulist[0];
        const int g = ((((h << 12) + (kb << 6) + r2) << 6) + half * 32);
        #pragma unroll
        for (int c = 0; c < 4; c++)
            cp16(khB[0] + rowoff + c * 16, gKh + g + c * 8);
    }
    CP_COMMIT();

    float oAcc[8][4] = {};
    float lsum0 = 0.f, lsum1 = 0.f;
    const int g8 = (lane >> 3) << 3;
    const int lr = lane & 7;

    for (int it = 0; it < ucnt; it++) {
        const int cur = it & 1;
        // V(it) loads (own group) into vhB[cur].
        {
            const int kb = ulist[it];
            const int g = ((((h << 12) + (kb << 6) + r2) << 6) + half * 32);
            #pragma unroll
            for (int c = 0; c < 4; c++)
                cp16(vhB[cur] + rowoff + c * 16, gVh + g + c * 8);
        }
        CP_COMMIT();
        // K(it+1) loads (own group; empty group on last iter keeps counts aligned).
        if (it + 1 < ucnt) {
            const int kb = ulist[it + 1];
            const int g = ((((h << 12) + (kb << 6) + r2) << 6) + half * 32);
            #pragma unroll
            for (int c = 0; c < 4; c++)
                cp16(khB[cur ^ 1] + rowoff + c * 16, gKh + g + c * 8);
        }
        CP_COMMIT();
        asm volatile("cp.async.wait_group 2;" ::: "memory");  // K(it) landed
        __syncthreads();

        const uint32_t kh = khB[cur];

        // ---- S = Qh Kh^T.
        float sC[8][4] = {};
        #pragma unroll
        for (int kk = 0; kk < 2; kk++) {
            #pragma unroll
            for (int nt = 0; nt < 8; nt++) {
                uint32_t baddr = (uint32_t)((8 * nt + lr) * TS + 32 * kk + g8) * 2;
                uint32_t bh[4];
                ldm_x4(bh, kh + baddr);
                mma16816(sC[nt], qf[2 * kk],     bh[0], bh[1]);
                mma16816(sC[nt], qf[2 * kk + 1], bh[2], bh[3]);
            }
        }

        // ---- ex2, l accumulate, pack P (single fp16).
        uint32_t ph[8][2];
        #pragma unroll
        for (int nt = 0; nt < 8; nt++) {
            float p0 = ex2f(sC[nt][0]), p1 = ex2f(sC[nt][1]);
            float p2 = ex2f(sC[nt][2]), p3 = ex2f(sC[nt][3]);
            lsum0 += p0 + p1; lsum1 += p2 + p3;
            ph[nt][0] = pack2h(p0, p1);
            ph[nt][1] = pack2h(p2, p3);
        }

        asm volatile("cp.async.wait_group 1;" ::: "memory");  // V(it) landed
        __syncthreads();

        // ---- O += Ph Vh.
        #pragma unroll
        for (int kk = 0; kk < 2; kk++) {
            uint32_t pa0[4] = { ph[4*kk][0], ph[4*kk][1], ph[4*kk+1][0], ph[4*kk+1][1] };
            uint32_t pa1[4] = { ph[4*kk+2][0], ph[4*kk+2][1], ph[4*kk+3][0], ph[4*kk+3][1] };
            #pragma unroll
            for (int nt = 0; nt < 8; nt++) {
                uint32_t baddr = (uint32_t)((32 * kk + g8 + lr) * TS + 8 * nt) * 2;
                uint32_t bh[4];
                ldm_x4_t(bh, vhB[cur] + baddr);
                mma16816(oAcc[nt], pa0, bh[0], bh[1]);
                mma16816(oAcc[nt], pa1, bh[2], bh[3]);
            }
        }
        // no tail sync (next iter writes vhB[cur^1] and khB[cur] only).
    }

    #pragma unroll
    for (int off = 1; off < 4; off <<= 1) {
        lsum0 += __shfl_xor_sync(0xffffffffu, lsum0, off, 4);
        lsum1 += __shfl_xor_sync(0xffffffffu, lsum1, off, 4);
    }
    const float inv0 = 1.f / lsum0, inv1 = 1.f / lsum1;

    {
        const int r0 = (qb << 6) + m0 + (lane >> 2);
        const int cc = (lane & 3) << 1;
        float* o0 = out + (((h << 12) + r0) << 6) + cc;
        float* o1 = o0 + (8 << 6);
        #pragma unroll
        for (int nt = 0; nt < 8; nt++) {
            *(float2*)(o0 + 8 * nt) = make_float2(oAcc[nt][0] * inv0, oAcc[nt][1] * inv0);
            *(float2*)(o1 + 8 * nt) = make_float2(oAcc[nt][2] * inv1, oAcc[nt][3] * inv1);
        }
    }
}

extern "C" void kernel_launch(void* const* d_in, const int* in_sizes, int n_in,
                              void* d_out, int out_size) {
    const float* q  = (const float*)d_in[0];
    const float* k  = (const float*)d_in[1];
    const float* v  = (const float*)d_in[2];
    const int* siq  = (const int*)d_in[3];
    const int* sik  = (const int*)d_in[4];
    float* out = (float*)d_out;

    const int pool_smem = 92160;
    const int attn_smem = 36864;
    cudaFuncSetAttribute(pool_gemm_kernel, cudaFuncAttributeMaxDynamicSharedMemorySize, pool_smem);
    cudaFuncSetAttribute(attn_hmma_kernel, cudaFuncAttributeMaxDynamicSharedMemorySize, attn_smem);

    split_prepass<<<1024, 256>>>(q, k, v);
    pool_gemm_kernel<<<dim3(16, 8), 256, pool_smem>>>(siq, sik);

    // attn with programmatic dependent launch: prologue (Q load + fragment
    // extraction) overlaps pool_gemm's tail; cudaGridDependencySynchronize()
    // inside the kernel gates the keep_bits read.
    cudaLaunchConfig_t cfg = {};
    cfg.gridDim = dim3(64, 8);
    cfg.blockDim = dim3(128);
    cfg.dynamicSmemBytes = attn_smem;
    cfg.stream = 0;
    cudaLaunchAttribute attrs[1];
    attrs[0].id = cudaLaunchAttributeProgrammaticStreamSerialization;
    attrs[0].val.programmaticStreamSerializationAllowed = 1;
    cfg.attrs = attrs;
    cfg.numAttrs = 1;
    cudaError_t err = cudaLaunchKernelEx(&cfg, attn_hmma_kernel, out);
    if (err != cudaSuccess) {
        // Fallback: plain launch (grid sync degenerates to a no-op wait).
        attn_hmma_kernel<<<dim3(64, 8), 128, attn_smem>>>(out);
    }
}